// round 7
// baseline (speedup 1.0000x reference)
#include <cuda_runtime.h>
#include <math_constants.h>

#define BB   2
#define NN   32768
#define NCC  1024
#define SS   32
#define MM   (NCC*SS)          // 32768

#define NN_WARPS  8            // warps per block in k_nn
#define QPW       8            // queries per warp
#define QPB       (NN_WARPS*QPW)   // 64 queries per block
#define CAP       256          // candidate list capacity per warp

// Scratch (no allocations allowed) ------------------------------------------
__device__ float4       g_xyzp [BB*NN];   // (x,y,z,|p|^2)
__device__ float4       g_ctr  [BB*NCC];  // (x,y,z,|c|^2)
__device__ int          g_assign[BB*NN];  // nearest-center id per xyz point
__device__ int          g_cnt [BB*NCC];
__device__ int          g_start[BB*NCC];  // global exclusive prefix over counts
__device__ int          g_cur [BB*NCC];   // scatter cursor
__device__ unsigned int g_rmax[BB*NCC];   // max member distance (float bits)
__device__ unsigned int g_rmm [BB];       // per-batch max of g_rmax (float bits)
__device__ float4       g_psort[BB*NN];   // xyz points sorted by (b, cluster)
__device__ float        g_mind[BB*MM];    // best squared distance per sphere point
__device__ float        g_acc[4];

// ---------------------------------------------------------------------------
__device__ __forceinline__ float warpMin(float v) {
    #pragma unroll
    for (int o = 16; o > 0; o >>= 1)
        v = fminf(v, __shfl_xor_sync(0xffffffffu, v, o));
    return v;
}

__inline__ __device__ float blockReduceSum(float v) {
    __shared__ float sw[32];
    #pragma unroll
    for (int o = 16; o > 0; o >>= 1) v += __shfl_down_sync(0xffffffffu, v, o);
    int lane = threadIdx.x & 31, w = threadIdx.x >> 5;
    if (lane == 0) sw[w] = v;
    __syncthreads();
    int nw = blockDim.x >> 5;
    v = (threadIdx.x < nw) ? sw[threadIdx.x] : 0.0f;
    if (w == 0) {
        #pragma unroll
        for (int o = 16; o > 0; o >>= 1) v += __shfl_down_sync(0xffffffffu, v, o);
    }
    return v;
}

// Pack inputs + init scratch --------------------------------------------------
__global__ void k_prep(const float* __restrict__ xyz, const float* __restrict__ ctr) {
    int i = blockIdx.x * blockDim.x + threadIdx.x;
    if (i < BB*NN) {
        float x = xyz[3*i+0], y = xyz[3*i+1], z = xyz[3*i+2];
        g_xyzp[i] = make_float4(x, y, z, x*x + y*y + z*z);
    }
    if (i < BB*NCC) {
        float x = ctr[3*i+0], y = ctr[3*i+1], z = ctr[3*i+2];
        g_ctr[i] = make_float4(x, y, z, x*x + y*y + z*z);
        g_cnt[i] = 0;
        g_rmax[i] = 0u;
    }
    if (i < BB) g_rmm[i] = 0u;
    if (i < 4) g_acc[i] = 0.0f;
}

// Part 1: xyz -> nearest center. Loss contrib + cluster assignment ------------
__global__ void k_p2c(const float* __restrict__ radius) {
    __shared__ float4 shc[NCC];
    const int b = blockIdx.y;
    const int n = blockIdx.x * blockDim.x + threadIdx.x;
    for (int i = threadIdx.x; i < NCC; i += blockDim.x)
        shc[i] = g_ctr[b*NCC + i];
    __syncthreads();

    float4 q = g_xyzp[b*NN + n];
    float ax = -2.0f*q.x, ay = -2.0f*q.y, az = -2.0f*q.z;
    float tmin = CUDART_INF_F;
    int idx = 0;
    #pragma unroll 4
    for (int c = 0; c < NCC; ++c) {
        float4 p = shc[c];
        float t = fmaf(ax, p.x, p.w);
        t = fmaf(ay, p.y, t);
        t = fmaf(az, p.z, t);
        if (t < tmin) { tmin = t; idx = c; }   // strict < : first-min == jnp.argmin
    }
    float cd = sqrtf(fmaxf(tmin + q.w, 1e-12f));
    float contrib = fmaxf(cd - radius[b*NCC + idx], 0.0f); // == |min(r-cd,0)|
    float s = blockReduceSum(contrib);
    if (threadIdx.x == 0) atomicAdd(&g_acc[b], s);

    g_assign[b*NN + n] = idx;
    atomicAdd(&g_cnt[b*NCC + idx], 1);
    atomicMax(&g_rmax[b*NCC + idx], __float_as_uint(cd));  // cd >= 0
}

// Exclusive prefix over all BB*NCC counts + per-batch radius max --------------
__global__ void k_scan() {
    __shared__ int sa[1024], sb[1024];
    const int t = threadIdx.x;
    int c0 = g_cnt[2*t], c1 = g_cnt[2*t+1];
    // per-batch max radius: clusters 2t,2t+1 share a batch
    unsigned rm = max(g_rmax[2*t], g_rmax[2*t+1]);   // nonneg float bits: int order ok
    atomicMax(&g_rmm[(2*t)/NCC], rm);
    sa[t] = c0 + c1;
    int* src = sa; int* dst = sb;
    #pragma unroll
    for (int off = 1; off < 1024; off <<= 1) {
        __syncthreads();
        int v = src[t];
        if (t >= off) v += src[t - off];
        dst[t] = v;
        int* tmp = src; src = dst; dst = tmp;
    }
    __syncthreads();
    int incl = src[t];
    int excl = incl - (c0 + c1);
    g_start[2*t]   = excl;       g_cur[2*t]   = excl;
    g_start[2*t+1] = excl + c0;  g_cur[2*t+1] = excl + c0;
}

// Scatter xyz points into cluster-sorted order --------------------------------
__global__ void k_scatter() {
    int i = blockIdx.x * blockDim.x + threadIdx.x;
    if (i >= BB*NN) return;
    int b = i / NN;
    int bc = b*NCC + g_assign[i];
    int pos = atomicAdd(&g_cur[bc], 1);
    g_psort[pos] = g_xyzp[i];
}

// Scan helper: distance term for one candidate cluster chunk (predicated) -----
__device__ __forceinline__ float candTerm(const float4* __restrict__ pts,
                                          int startv, int cnt, int o,
                                          float ax, float ay, float az) {
    if (o < cnt) {
        float4 p = pts[startv + o];
        float t = fmaf(ax, p.x, p.w);
        t = fmaf(ay, p.y, t);
        t = fmaf(az, p.z, t);
        return t;
    }
    return CUDART_INF_F;
}

// Scan 4 clusters with MLP=4 (s.y==0 disables a slot) -------------------------
__device__ __forceinline__ void scanGroup4(const float4* __restrict__ pts,
                                           int2 s0, int2 s1, int2 s2, int2 s3,
                                           int lane, float ax, float ay, float az,
                                           float& lmin) {
    lmin = fminf(lmin, candTerm(pts, s0.x, s0.y, lane, ax, ay, az));
    lmin = fminf(lmin, candTerm(pts, s1.x, s1.y, lane, ax, ay, az));
    lmin = fminf(lmin, candTerm(pts, s2.x, s2.y, lane, ax, ay, az));
    lmin = fminf(lmin, candTerm(pts, s3.x, s3.y, lane, ax, ay, az));
    int mx = max(max(s0.y, s1.y), max(s2.y, s3.y));
    for (int o = lane + 32; o < mx; o += 32) {
        lmin = fminf(lmin, candTerm(pts, s0.x, s0.y, o, ax, ay, az));
        lmin = fminf(lmin, candTerm(pts, s1.x, s1.y, o, ax, ay, az));
        lmin = fminf(lmin, candTerm(pts, s2.x, s2.y, o, ax, ay, az));
        lmin = fminf(lmin, candTerm(pts, s3.x, s3.y, o, ax, ay, az));
    }
}

// Unsorted fallback scan over a packed candidate list --------------------------
__device__ __forceinline__ void scanCands(const float4* __restrict__ pts,
                                          const int2* __restrict__ shcs,
                                          const unsigned* __restrict__ list,
                                          int n, int lane,
                                          float ax, float ay, float az,
                                          float& lmin) {
    int ci = 0;
    for (; ci + 4 <= n; ci += 4) {
        int2 s0 = shcs[list[ci+0] & 1023u];
        int2 s1 = shcs[list[ci+1] & 1023u];
        int2 s2 = shcs[list[ci+2] & 1023u];
        int2 s3 = shcs[list[ci+3] & 1023u];
        scanGroup4(pts, s0, s1, s2, s3, lane, ax, ay, az, lmin);
    }
    for (; ci < n; ++ci) {
        int2 s0 = shcs[list[ci] & 1023u];
        for (int o = lane; o < s0.y; o += 32)
            lmin = fminf(lmin, candTerm(pts, s0.x, s0.y, o, ax, ay, az));
    }
}

// Part 2: sphere point -> exact NN via center-cluster pruning. 1 warp/query. --
__global__ void __launch_bounds__(32*NN_WARPS)
k_nn(const float* __restrict__ sp) {
    __shared__ float4 shc[NCC];    // centers (x,y,z,|c|^2); w=+inf if empty
    __shared__ int2   shcs[NCC];   // (start, count)
    __shared__ float  shr[NCC];    // padded cluster radius
    __shared__ unsigned shlist[NN_WARPS][CAP];  // packed (d2|cid) per warp
    const int tid  = threadIdx.x;
    const int lane = tid & 31;
    const int warp = tid >> 5;
    const int qblock = blockIdx.x * QPB;
    const int b = qblock / MM;     // QPB divides MM, block never straddles batches

    for (int i = tid; i < NCC; i += 32*NN_WARPS) {
        int cnt = g_cnt[b*NCC + i];
        float4 c = g_ctr[b*NCC + i];
        if (cnt == 0) c.w = CUDART_INF_F;   // empty clusters can never seed/admit
        shc[i]  = c;
        shcs[i] = make_int2(g_start[b*NCC + i], cnt);
        shr[i]  = __uint_as_float(g_rmax[b*NCC + i]) * 1.000002f + 1e-6f;
    }
    __syncthreads();
    const float shrmax = __uint_as_float(g_rmm[b]) * 1.000002f + 1e-6f;

    const float4* __restrict__ pts = g_psort;
    unsigned* const mylist = shlist[warp];

    for (int qi = 0; qi < QPW; ++qi) {
        const int q = qblock + warp*QPW + qi;       // global sphere-point index
        const float* sq = sp + (long long)q * 3;
        float qx = sq[0], qy = sq[1], qz = sq[2];   // warp-broadcast loads
        float ax = -2.0f*qx, ay = -2.0f*qy, az = -2.0f*qz;
        float qw = qx*qx + qy*qy + qz*qz;

        // Phase A: nearest non-empty center via packed REDUX argmin
        unsigned pk = 0xFFFFFFFFu;
        #pragma unroll
        for (int k = 0; k < 32; ++k) {
            const int cid = k*32 + lane;
            float4 c = shc[cid];
            float t = fmaf(ax, c.x, c.w);
            t = fmaf(ay, c.y, t);
            t = fmaf(az, c.z, t);
            float d2 = fmaxf(t + qw, 0.0f);         // +inf for empty clusters
            unsigned v = (__float_as_uint(d2) & 0xFFFFFC00u) | (unsigned)cid;
            pk = min(pk, v);
        }
        pk = __reduce_min_sync(0xffffffffu, pk);
        const int cidx0 = (int)(pk & 1023u);

        // Phase B: seed best from nearest non-empty cluster
        float lmin = CUDART_INF_F;
        {
            int2 sc = shcs[cidx0];
            for (int o = lane; o < sc.y; o += 32) {
                float4 p = pts[sc.x + o];
                float t = fmaf(ax, p.x, p.w);
                t = fmaf(ay, p.y, t);
                t = fmaf(az, p.z, t);
                lmin = fminf(lmin, t);
            }
        }
        float best = sqrtf(fmaxf(warpMin(lmin) + qw, 0.0f));

        // Phase C1: build packed candidate list (d2_trunc | cid); flush if full
        int nc = 0;
        #pragma unroll
        for (int k = 0; k < 32; ++k) {
            const int cid = k*32 + lane;
            float4 c = shc[cid];
            float t = fmaf(ax, c.x, c.w);
            t = fmaf(ay, c.y, t);
            t = fmaf(az, c.z, t);
            float d2 = fmaxf(t + qw, 0.0f);
            float thr = best + shr[cid];
            bool pred = (cid != cidx0) && (d2 < thr*thr);  // empty: d2=+inf -> false
            unsigned m = __ballot_sync(0xffffffffu, pred);
            if (pred) {
                int off = __popc(m & ((1u << lane) - 1u));
                mylist[nc + off] = (__float_as_uint(d2) & 0xFFFFFC00u) | (unsigned)cid;
            }
            nc += __popc(m);
            if (nc > CAP - 32) {                     // very rare: flush, stay exact
                __syncwarp();
                scanCands(pts, shcs, mylist, nc, lane, ax, ay, az, lmin);
                nc = 0;
            }
        }
        __syncwarp();

        if (nc <= 32) {
            // Phase C2a: bitonic-sort candidates by center distance (ascending)
            unsigned v = (lane < nc) ? mylist[lane] : 0xFFFFFFFFu;
            #pragma unroll
            for (int kk = 2; kk <= 32; kk <<= 1) {
                #pragma unroll
                for (int j = kk >> 1; j > 0; j >>= 1) {
                    unsigned o = __shfl_xor_sync(0xffffffffu, v, j);
                    bool takeMin = (((lane & j) == 0) == ((lane & kk) == 0));
                    v = takeMin ? min(v, o) : max(v, o);
                }
            }
            // Phase C2b: scan ascending, running-best re-check + early break
            for (int ci = 0; ci < nc; ci += 4) {
                best = sqrtf(fmaxf(warpMin(lmin) + qw, 0.0f));
                float brk = best + shrmax;
                unsigned e0 = __shfl_sync(0xffffffffu, v, ci);
                if (__uint_as_float(e0 & 0xFFFFFC00u) >= brk*brk) break;
                int2 s[4];
                #pragma unroll
                for (int j = 0; j < 4; ++j) {
                    unsigned e = __shfl_sync(0xffffffffu, v, min(ci + j, 31));
                    int cid = (int)(e & 1023u);
                    float d2 = __uint_as_float(e & 0xFFFFFC00u);
                    float th = best + shr[cid];
                    bool adm = (ci + j < nc) && (d2 < th*th);
                    s[j] = adm ? shcs[cid] : make_int2(0, 0);
                }
                scanGroup4(pts, s[0], s[1], s[2], s[3], lane, ax, ay, az, lmin);
            }
        } else {
            // Fallback (rare): unsorted scan
            scanCands(pts, shcs, mylist, nc, lane, ax, ay, az, lmin);
        }

        float best2 = warpMin(lmin) + qw;
        if (lane == 0) g_mind[q] = fmaxf(best2, 0.0f);
    }
}

// Epilogue: one warp per center: max over S, then sum over centers ------------
__global__ void k_c2p() {
    const int lane = threadIdx.x & 31;
    const int wid  = (blockIdx.x * blockDim.x + threadIdx.x) >> 5;  // 0..BB*NCC-1
    float v = sqrtf(fmaxf(g_mind[wid*SS + lane], 1e-12f));
    #pragma unroll
    for (int o = 16; o > 0; o >>= 1)
        v = fmaxf(v, __shfl_xor_sync(0xffffffffu, v, o));
    if (lane == 0) atomicAdd(&g_acc[2 + wid/NCC], v);
}

// Final scalar ----------------------------------------------------------------
__global__ void k_final(float* out) {
    float r = 0.0f;
    #pragma unroll
    for (int b = 0; b < BB; ++b)
        r += g_acc[b] * (1.0f/NN) + g_acc[2 + b] * (1.0f/NCC);
    out[0] = r * (1.0f/BB);
}

// ---------------------------------------------------------------------------
extern "C" void kernel_launch(void* const* d_in, const int* in_sizes, int n_in,
                              void* d_out, int out_size) {
    const float* centers = (const float*)d_in[0];
    const float* radius  = (const float*)d_in[1];
    const float* xyz     = (const float*)d_in[2];
    const float* sp      = (const float*)d_in[3];
    float* out = (float*)d_out;

    k_prep<<<(BB*NN + 255)/256, 256>>>(xyz, centers);
    k_p2c<<<dim3(NN/256, BB), 256>>>(radius);
    k_scan<<<1, 1024>>>();
    k_scatter<<<(BB*NN)/256, 256>>>();
    k_nn<<<(BB*MM)/QPB, 32*NN_WARPS>>>(sp);
    k_c2p<<<dim3((BB*NCC*32)/256), 256>>>();
    k_final<<<1, 1>>>(out);
}

// round 8
// speedup vs baseline: 1.5477x; 1.5477x over previous
#include <cuda_runtime.h>
#include <math_constants.h>

#define BB   2
#define NN   32768
#define NCC  1024
#define SS   32
#define MM   (NCC*SS)          // 32768

#define NN_WARPS  8            // warps per block in k_nn
#define QPW       8            // queries per warp
#define QPB       (NN_WARPS*QPW)   // 64 queries per block

// Scratch (no allocations allowed) ------------------------------------------
__device__ float4       g_xyzp [BB*NN];   // (x,y,z,|p|^2)
__device__ float4       g_ctr  [BB*NCC];  // (x,y,z,|c|^2)
__device__ int          g_assign[BB*NN];  // nearest-center id per xyz point
__device__ int          g_cnt [BB*NCC];
__device__ int          g_start[BB*NCC];
__device__ int          g_cur [BB*NCC];
__device__ unsigned int g_rmax[BB*NCC];   // max member distance (float bits)
__device__ float4       g_psort[BB*NN];   // xyz points sorted by (b, cluster)
// query sort
__device__ int          g_qseed[BB*MM];   // seed cluster per sphere point
__device__ int          g_qcnt [BB*NCC];
__device__ int          g_qcur [BB*NCC];
__device__ unsigned     g_qkey [BB*MM];   // sorted: (cid<<16) | q_local
__device__ float4       g_qpt  [BB*MM];   // sorted: (x,y,z,|q|^2)
__device__ float        g_mind[BB*MM];    // best squared distance per sphere point
__device__ float        g_acc[4];

// ---------------------------------------------------------------------------
__device__ __forceinline__ float warpMin(float v) {
    #pragma unroll
    for (int o = 16; o > 0; o >>= 1)
        v = fminf(v, __shfl_xor_sync(0xffffffffu, v, o));
    return v;
}

__inline__ __device__ float blockReduceSum(float v) {
    __shared__ float sw[32];
    #pragma unroll
    for (int o = 16; o > 0; o >>= 1) v += __shfl_down_sync(0xffffffffu, v, o);
    int lane = threadIdx.x & 31, w = threadIdx.x >> 5;
    if (lane == 0) sw[w] = v;
    __syncthreads();
    int nw = blockDim.x >> 5;
    v = (threadIdx.x < nw) ? sw[threadIdx.x] : 0.0f;
    if (w == 0) {
        #pragma unroll
        for (int o = 16; o > 0; o >>= 1) v += __shfl_down_sync(0xffffffffu, v, o);
    }
    return v;
}

// Pack inputs + init scratch --------------------------------------------------
__global__ void k_prep(const float* __restrict__ xyz, const float* __restrict__ ctr) {
    int i = blockIdx.x * blockDim.x + threadIdx.x;
    if (i < BB*NN) {
        float x = xyz[3*i+0], y = xyz[3*i+1], z = xyz[3*i+2];
        g_xyzp[i] = make_float4(x, y, z, x*x + y*y + z*z);
    }
    if (i < BB*NCC) {
        float x = ctr[3*i+0], y = ctr[3*i+1], z = ctr[3*i+2];
        g_ctr[i] = make_float4(x, y, z, x*x + y*y + z*z);
        g_cnt[i] = 0;
        g_qcnt[i] = 0;
        g_rmax[i] = 0u;
    }
    if (i < 4) g_acc[i] = 0.0f;
}

// Part 1: xyz -> nearest center. Loss contrib + cluster assignment ------------
__global__ void k_p2c(const float* __restrict__ radius) {
    __shared__ float4 shc[NCC];
    const int b = blockIdx.y;
    const int n = blockIdx.x * blockDim.x + threadIdx.x;
    for (int i = threadIdx.x; i < NCC; i += blockDim.x)
        shc[i] = g_ctr[b*NCC + i];
    __syncthreads();

    float4 q = g_xyzp[b*NN + n];
    float ax = -2.0f*q.x, ay = -2.0f*q.y, az = -2.0f*q.z;
    float tmin = CUDART_INF_F;
    int idx = 0;
    #pragma unroll 4
    for (int c = 0; c < NCC; ++c) {
        float4 p = shc[c];
        float t = fmaf(ax, p.x, p.w);
        t = fmaf(ay, p.y, t);
        t = fmaf(az, p.z, t);
        if (t < tmin) { tmin = t; idx = c; }   // strict < : first-min == jnp.argmin
    }
    float cd = sqrtf(fmaxf(tmin + q.w, 1e-12f));
    float contrib = fmaxf(cd - radius[b*NCC + idx], 0.0f); // == |min(r-cd,0)|
    float s = blockReduceSum(contrib);
    if (threadIdx.x == 0) atomicAdd(&g_acc[b], s);

    g_assign[b*NN + n] = idx;
    atomicAdd(&g_cnt[b*NCC + idx], 1);
    atomicMax(&g_rmax[b*NCC + idx], __float_as_uint(cd));  // cd >= 0
}

// Exclusive prefix over point counts ------------------------------------------
__global__ void k_scan() {
    __shared__ int sa[1024], sb[1024];
    const int t = threadIdx.x;
    int c0 = g_cnt[2*t], c1 = g_cnt[2*t+1];
    sa[t] = c0 + c1;
    int* src = sa; int* dst = sb;
    #pragma unroll
    for (int off = 1; off < 1024; off <<= 1) {
        __syncthreads();
        int v = src[t];
        if (t >= off) v += src[t - off];
        dst[t] = v;
        int* tmp = src; src = dst; dst = tmp;
    }
    __syncthreads();
    int incl = src[t];
    int excl = incl - (c0 + c1);
    g_start[2*t]   = excl;       g_cur[2*t]   = excl;
    g_start[2*t+1] = excl + c0;  g_cur[2*t+1] = excl + c0;
}

// Scatter xyz points into cluster-sorted order --------------------------------
__global__ void k_scatter() {
    int i = blockIdx.x * blockDim.x + threadIdx.x;
    if (i >= BB*NN) return;
    int b = i / NN;
    int bc = b*NCC + g_assign[i];
    int pos = atomicAdd(&g_cur[bc], 1);
    g_psort[pos] = g_xyzp[i];
}

// Query prepass: seed cluster (nearest non-empty center) per sphere point -----
__global__ void k_qprep(const float* __restrict__ sp) {
    __shared__ float4 shc[NCC];
    const int b = blockIdx.y;
    const int m = blockIdx.x * blockDim.x + threadIdx.x;
    for (int i = threadIdx.x; i < NCC; i += blockDim.x) {
        float4 c = g_ctr[b*NCC + i];
        if (g_cnt[b*NCC + i] == 0) c.w = CUDART_INF_F;  // never seed empty
        shc[i] = c;
    }
    __syncthreads();

    const float* p = sp + ((long long)b*MM + m) * 3;
    float x = p[0], y = p[1], z = p[2];
    float ax = -2.0f*x, ay = -2.0f*y, az = -2.0f*z;
    float tmin = CUDART_INF_F;
    int idx = 0;
    #pragma unroll 4
    for (int c = 0; c < NCC; ++c) {
        float4 cc = shc[c];
        float t = fmaf(ax, cc.x, cc.w);
        t = fmaf(ay, cc.y, t);
        t = fmaf(az, cc.z, t);
        if (t < tmin) { tmin = t; idx = c; }
    }
    g_qseed[b*MM + m] = idx;
    atomicAdd(&g_qcnt[b*NCC + idx], 1);
}

// Prefix over query counts ------------------------------------------------------
__global__ void k_qscan() {
    __shared__ int sa[1024], sb[1024];
    const int t = threadIdx.x;
    int c0 = g_qcnt[2*t], c1 = g_qcnt[2*t+1];
    sa[t] = c0 + c1;
    int* src = sa; int* dst = sb;
    #pragma unroll
    for (int off = 1; off < 1024; off <<= 1) {
        __syncthreads();
        int v = src[t];
        if (t >= off) v += src[t - off];
        dst[t] = v;
        int* tmp = src; src = dst; dst = tmp;
    }
    __syncthreads();
    int incl = src[t];
    int excl = incl - (c0 + c1);
    g_qcur[2*t]   = excl;
    g_qcur[2*t+1] = excl + c0;
}

// Scatter queries into seed-sorted order ---------------------------------------
__global__ void k_qscatter(const float* __restrict__ sp) {
    int i = blockIdx.x * blockDim.x + threadIdx.x;
    if (i >= BB*MM) return;
    int b = i / MM, m = i - b*MM;
    int cid = g_qseed[i];
    int pos = atomicAdd(&g_qcur[b*NCC + cid], 1);
    const float* p = sp + (long long)i * 3;
    float x = p[0], y = p[1], z = p[2];
    g_qkey[pos] = ((unsigned)cid << 16) | (unsigned)m;
    g_qpt[pos]  = make_float4(x, y, z, x*x + y*y + z*z);
}

// Scan helper: distance term for one candidate cluster chunk (predicated) -----
__device__ __forceinline__ float candTerm(const float4* __restrict__ pts,
                                          int startv, int cnt, int o,
                                          float ax, float ay, float az) {
    if (o < cnt) {
        float4 p = pts[startv + o];
        float t = fmaf(ax, p.x, p.w);
        t = fmaf(ay, p.y, t);
        t = fmaf(az, p.z, t);
        return t;
    }
    return CUDART_INF_F;
}

// Scan a candidate list, 4 clusters at a time (MLP=4) -------------------------
__device__ __forceinline__ void scanCands(const float4* __restrict__ pts,
                                          const int2* __restrict__ shcs,
                                          const unsigned short* __restrict__ list,
                                          int n, int lane,
                                          float ax, float ay, float az,
                                          float& lmin) {
    int ci = 0;
    for (; ci + 4 <= n; ci += 4) {
        int2 s0 = shcs[list[ci+0]];
        int2 s1 = shcs[list[ci+1]];
        int2 s2 = shcs[list[ci+2]];
        int2 s3 = shcs[list[ci+3]];
        lmin = fminf(lmin, candTerm(pts, s0.x, s0.y, lane, ax, ay, az));
        lmin = fminf(lmin, candTerm(pts, s1.x, s1.y, lane, ax, ay, az));
        lmin = fminf(lmin, candTerm(pts, s2.x, s2.y, lane, ax, ay, az));
        lmin = fminf(lmin, candTerm(pts, s3.x, s3.y, lane, ax, ay, az));
        int mx = max(max(s0.y, s1.y), max(s2.y, s3.y));
        for (int o = lane + 32; o < mx; o += 32) {
            lmin = fminf(lmin, candTerm(pts, s0.x, s0.y, o, ax, ay, az));
            lmin = fminf(lmin, candTerm(pts, s1.x, s1.y, o, ax, ay, az));
            lmin = fminf(lmin, candTerm(pts, s2.x, s2.y, o, ax, ay, az));
            lmin = fminf(lmin, candTerm(pts, s3.x, s3.y, o, ax, ay, az));
        }
    }
    for (; ci < n; ++ci) {
        int2 s0 = shcs[list[ci]];
        for (int o = lane; o < s0.y; o += 32)
            lmin = fminf(lmin, candTerm(pts, s0.x, s0.y, o, ax, ay, az));
    }
}

// Part 2: exact NN over seed-sorted queries. 1 warp per query. ----------------
__global__ void __launch_bounds__(32*NN_WARPS)
k_nn() {
    __shared__ float4 shc[NCC];    // centers; w=+inf if empty
    __shared__ int2   shcs[NCC];   // (start, count)
    __shared__ float  shr[NCC];    // padded cluster radius
    __shared__ unsigned short shlist[NN_WARPS][NCC];
    const int tid  = threadIdx.x;
    const int lane = tid & 31;
    const int warp = tid >> 5;
    const int qblock = blockIdx.x * QPB;
    const int b = qblock / MM;     // sorted arrays are batch-major

    for (int i = tid; i < NCC; i += 32*NN_WARPS) {
        int cnt = g_cnt[b*NCC + i];
        float4 c = g_ctr[b*NCC + i];
        if (cnt == 0) c.w = CUDART_INF_F;
        shc[i]  = c;
        shcs[i] = make_int2(g_start[b*NCC + i], cnt);
        shr[i]  = __uint_as_float(g_rmax[b*NCC + i]) * 1.000002f + 1e-6f;
    }
    __syncthreads();

    const float4* __restrict__ pts = g_psort;
    unsigned short* const mylist = shlist[warp];

    for (int qi = 0; qi < QPW; ++qi) {
        const int qs = qblock + warp*QPW + qi;      // sorted position
        const unsigned key = g_qkey[qs];            // broadcast
        const int cidx0 = (int)(key >> 16);
        const int qloc  = (int)(key & 0xFFFFu);
        float4 qp = g_qpt[qs];                      // broadcast LDG.128
        float ax = -2.0f*qp.x, ay = -2.0f*qp.y, az = -2.0f*qp.z;
        float qw = qp.w;

        // Phase B: seed best from the (precomputed) nearest non-empty cluster
        float lmin = CUDART_INF_F;
        {
            int2 sc = shcs[cidx0];
            for (int o = lane; o < sc.y; o += 32) {
                float4 p = pts[sc.x + o];
                float t = fmaf(ax, p.x, p.w);
                t = fmaf(ay, p.y, t);
                t = fmaf(az, p.z, t);
                lmin = fminf(lmin, t);
            }
        }
        const float best = sqrtf(fmaxf(warpMin(lmin) + qw, 0.0f));

        // Phase C1: build candidate list (center distances recomputed)
        int nc = 0;
        #pragma unroll
        for (int k = 0; k < 32; ++k) {
            const int cid = k*32 + lane;
            float4 c = shc[cid];
            float t = fmaf(ax, c.x, c.w);
            t = fmaf(ay, c.y, t);
            t = fmaf(az, c.z, t);
            float thr = best + shr[cid];
            bool pred = (cid != cidx0) && (t + qw < thr*thr);  // empty: t=+inf
            unsigned m = __ballot_sync(0xffffffffu, pred);
            if (pred) {
                int off = __popc(m & ((1u << lane) - 1u));
                mylist[nc + off] = (unsigned short)cid;
            }
            nc += __popc(m);
        }
        __syncwarp();

        // Phase C2: scan candidates 4 at a time (MLP=4)
        scanCands(pts, shcs, mylist, nc, lane, ax, ay, az, lmin);

        float best2 = warpMin(lmin) + qw;
        if (lane == 0) g_mind[b*MM + qloc] = fmaxf(best2, 0.0f);
    }
}

// Epilogue: one warp per center: max over S, then sum over centers ------------
__global__ void k_c2p() {
    const int lane = threadIdx.x & 31;
    const int wid  = (blockIdx.x * blockDim.x + threadIdx.x) >> 5;  // 0..BB*NCC-1
    float v = sqrtf(fmaxf(g_mind[wid*SS + lane], 1e-12f));
    #pragma unroll
    for (int o = 16; o > 0; o >>= 1)
        v = fmaxf(v, __shfl_xor_sync(0xffffffffu, v, o));
    if (lane == 0) atomicAdd(&g_acc[2 + wid/NCC], v);
}

// Final scalar ----------------------------------------------------------------
__global__ void k_final(float* out) {
    float r = 0.0f;
    #pragma unroll
    for (int b = 0; b < BB; ++b)
        r += g_acc[b] * (1.0f/NN) + g_acc[2 + b] * (1.0f/NCC);
    out[0] = r * (1.0f/BB);
}

// ---------------------------------------------------------------------------
extern "C" void kernel_launch(void* const* d_in, const int* in_sizes, int n_in,
                              void* d_out, int out_size) {
    const float* centers = (const float*)d_in[0];
    const float* radius  = (const float*)d_in[1];
    const float* xyz     = (const float*)d_in[2];
    const float* sp      = (const float*)d_in[3];
    float* out = (float*)d_out;

    k_prep<<<(BB*NN + 255)/256, 256>>>(xyz, centers);
    k_p2c<<<dim3(NN/256, BB), 256>>>(radius);
    k_scan<<<1, 1024>>>();
    k_scatter<<<(BB*NN)/256, 256>>>();
    k_qprep<<<dim3(MM/256, BB), 256>>>(sp);
    k_qscan<<<1, 1024>>>();
    k_qscatter<<<(BB*MM)/256, 256>>>(sp);
    k_nn<<<(BB*MM)/QPB, 32*NN_WARPS>>>();
    k_c2p<<<dim3((BB*NCC*32)/256), 256>>>();
    k_final<<<1, 1>>>(out);
}

// round 9
// speedup vs baseline: 2.0735x; 1.3397x over previous
#include <cuda_runtime.h>
#include <math_constants.h>

#define BB   2
#define NN   32768
#define NCC  1024
#define SS   32
#define MM   (NCC*SS)          // 32768

#define NN_WARPS  8            // warps per block in k_nn
#define GQ        8            // queries per warp (processed together)
#define QPB       (NN_WARPS*GQ)    // 64 queries per block

// Scratch (no allocations allowed) ------------------------------------------
__device__ float4       g_xyzp [BB*NN];   // (x,y,z,|p|^2)
__device__ float4       g_ctr  [BB*NCC];  // (x,y,z,|c|^2)
__device__ int          g_assign[BB*NN];
__device__ int          g_cnt [BB*NCC];
__device__ int          g_start[BB*NCC];
__device__ int          g_cur [BB*NCC];
__device__ unsigned int g_rmax[BB*NCC];   // max member distance (float bits)
__device__ float4       g_psort[BB*NN];   // xyz points sorted by (b, cluster)
// query sort
__device__ int          g_qseed[BB*MM];
__device__ int          g_qcnt [BB*NCC];
__device__ int          g_qcur [BB*NCC];
__device__ unsigned     g_qkey [BB*MM];   // sorted: (cid<<16) | q_local
__device__ float4       g_qpt  [BB*MM];   // sorted: (x,y,z,|q|^2)
__device__ float        g_mind[BB*MM];
__device__ float        g_acc[4];

// ---------------------------------------------------------------------------
__device__ __forceinline__ float warpMin(float v) {
    #pragma unroll
    for (int o = 16; o > 0; o >>= 1)
        v = fminf(v, __shfl_xor_sync(0xffffffffu, v, o));
    return v;
}

__inline__ __device__ float blockReduceSum(float v) {
    __shared__ float sw[32];
    #pragma unroll
    for (int o = 16; o > 0; o >>= 1) v += __shfl_down_sync(0xffffffffu, v, o);
    int lane = threadIdx.x & 31, w = threadIdx.x >> 5;
    if (lane == 0) sw[w] = v;
    __syncthreads();
    int nw = blockDim.x >> 5;
    v = (threadIdx.x < nw) ? sw[threadIdx.x] : 0.0f;
    if (w == 0) {
        #pragma unroll
        for (int o = 16; o > 0; o >>= 1) v += __shfl_down_sync(0xffffffffu, v, o);
    }
    return v;
}

// Pack inputs + init scratch --------------------------------------------------
__global__ void k_prep(const float* __restrict__ xyz, const float* __restrict__ ctr) {
    int i = blockIdx.x * blockDim.x + threadIdx.x;
    if (i < BB*NN) {
        float x = xyz[3*i+0], y = xyz[3*i+1], z = xyz[3*i+2];
        g_xyzp[i] = make_float4(x, y, z, x*x + y*y + z*z);
    }
    if (i < BB*NCC) {
        float x = ctr[3*i+0], y = ctr[3*i+1], z = ctr[3*i+2];
        g_ctr[i] = make_float4(x, y, z, x*x + y*y + z*z);
        g_cnt[i] = 0;
        g_qcnt[i] = 0;
        g_rmax[i] = 0u;
    }
    if (i < 4) g_acc[i] = 0.0f;
}

// Part 1: xyz -> nearest center. Loss contrib + cluster assignment ------------
__global__ void k_p2c(const float* __restrict__ radius) {
    __shared__ float4 shc[NCC];
    const int b = blockIdx.y;
    const int n = blockIdx.x * blockDim.x + threadIdx.x;
    for (int i = threadIdx.x; i < NCC; i += blockDim.x)
        shc[i] = g_ctr[b*NCC + i];
    __syncthreads();

    float4 q = g_xyzp[b*NN + n];
    float ax = -2.0f*q.x, ay = -2.0f*q.y, az = -2.0f*q.z;
    float tmin = CUDART_INF_F;
    int idx = 0;
    #pragma unroll 4
    for (int c = 0; c < NCC; ++c) {
        float4 p = shc[c];
        float t = fmaf(ax, p.x, p.w);
        t = fmaf(ay, p.y, t);
        t = fmaf(az, p.z, t);
        if (t < tmin) { tmin = t; idx = c; }   // strict < : first-min == jnp.argmin
    }
    float cd = sqrtf(fmaxf(tmin + q.w, 1e-12f));
    float contrib = fmaxf(cd - radius[b*NCC + idx], 0.0f);
    float s = blockReduceSum(contrib);
    if (threadIdx.x == 0) atomicAdd(&g_acc[b], s);

    g_assign[b*NN + n] = idx;
    atomicAdd(&g_cnt[b*NCC + idx], 1);
    atomicMax(&g_rmax[b*NCC + idx], __float_as_uint(cd));
}

// Query prepass: seed cluster (nearest non-empty center) per sphere point -----
__global__ void k_qprep(const float* __restrict__ sp) {
    __shared__ float4 shc[NCC];
    const int b = blockIdx.y;
    const int m = blockIdx.x * blockDim.x + threadIdx.x;
    for (int i = threadIdx.x; i < NCC; i += blockDim.x) {
        float4 c = g_ctr[b*NCC + i];
        if (g_cnt[b*NCC + i] == 0) c.w = CUDART_INF_F;
        shc[i] = c;
    }
    __syncthreads();

    const float* p = sp + ((long long)b*MM + m) * 3;
    float x = p[0], y = p[1], z = p[2];
    float ax = -2.0f*x, ay = -2.0f*y, az = -2.0f*z;
    float tmin = CUDART_INF_F;
    int idx = 0;
    #pragma unroll 4
    for (int c = 0; c < NCC; ++c) {
        float4 cc = shc[c];
        float t = fmaf(ax, cc.x, cc.w);
        t = fmaf(ay, cc.y, t);
        t = fmaf(az, cc.z, t);
        if (t < tmin) { tmin = t; idx = c; }
    }
    g_qseed[b*MM + m] = idx;
    atomicAdd(&g_qcnt[b*NCC + idx], 1);
}

// Fused prefix scans: point counts then query counts ---------------------------
__device__ __forceinline__ void scan2048(const int* cnt, int* out0, int* out1,
                                         int* sa, int* sb, bool dual) {
    const int t = threadIdx.x;
    int c0 = cnt[2*t], c1 = cnt[2*t+1];
    sa[t] = c0 + c1;
    int* src = sa; int* dst = sb;
    #pragma unroll
    for (int off = 1; off < 1024; off <<= 1) {
        __syncthreads();
        int v = src[t];
        if (t >= off) v += src[t - off];
        dst[t] = v;
        int* tmp = src; src = dst; dst = tmp;
    }
    __syncthreads();
    int incl = src[t];
    int excl = incl - (c0 + c1);
    out0[2*t]   = excl;       out0[2*t+1] = excl + c0;
    if (dual) { out1[2*t] = excl; out1[2*t+1] = excl + c0; }
    __syncthreads();
}

__global__ void k_scan() {
    __shared__ int sa[1024], sb[1024];
    scan2048(g_cnt,  g_start, g_cur, sa, sb, true);   // points: start + cursor
    scan2048(g_qcnt, g_qcur,  0,     sa, sb, false);  // queries: cursor only
}

// Scatter xyz points into cluster-sorted order --------------------------------
__global__ void k_scatter() {
    int i = blockIdx.x * blockDim.x + threadIdx.x;
    if (i >= BB*NN) return;
    int b = i / NN;
    int bc = b*NCC + g_assign[i];
    int pos = atomicAdd(&g_cur[bc], 1);
    g_psort[pos] = g_xyzp[i];
}

// Scatter queries into seed-sorted order ---------------------------------------
__global__ void k_qscatter(const float* __restrict__ sp) {
    int i = blockIdx.x * blockDim.x + threadIdx.x;
    if (i >= BB*MM) return;
    int b = i / MM, m = i - b*MM;
    int cid = g_qseed[i];
    int pos = atomicAdd(&g_qcur[b*NCC + cid], 1);
    const float* p = sp + (long long)i * 3;
    float x = p[0], y = p[1], z = p[2];
    g_qkey[pos] = ((unsigned)cid << 16) | (unsigned)m;
    g_qpt[pos]  = make_float4(x, y, z, x*x + y*y + z*z);
}

// Part 2: exact NN, 8 sorted queries per warp share each cluster load ----------
__global__ void __launch_bounds__(32*NN_WARPS)
k_nn() {
    __shared__ float4 shc[NCC];    // centers; w=+inf if empty
    __shared__ int2   shcs[NCC];   // (start, count)
    __shared__ float  shr[NCC];    // padded cluster radius
    __shared__ unsigned short shlist[NN_WARPS][NCC];
    const int tid  = threadIdx.x;
    const int lane = tid & 31;
    const int warp = tid >> 5;
    const int qbase = blockIdx.x * QPB + warp * GQ;   // this warp's 8 sorted queries
    const int b = (blockIdx.x * QPB) / MM;            // QPB divides MM

    for (int i = tid; i < NCC; i += 32*NN_WARPS) {
        int cnt = g_cnt[b*NCC + i];
        float4 c = g_ctr[b*NCC + i];
        if (cnt == 0) c.w = CUDART_INF_F;
        shc[i]  = c;
        shcs[i] = make_int2(g_start[b*NCC + i], cnt);
        shr[i]  = __uint_as_float(g_rmax[b*NCC + i]) * 1.000002f + 1e-6f;
    }
    __syncthreads();

    const float4* __restrict__ pts = g_psort;
    unsigned short* const mylist = shlist[warp];

    // Load 8 queries (uniform broadcast loads)
    float ax[GQ], ay[GQ], az[GQ], qw[GQ], lmin[GQ];
    int   seed[GQ];
    #pragma unroll
    for (int q = 0; q < GQ; ++q) {
        float4 qp = g_qpt[qbase + q];
        ax[q] = -2.0f*qp.x; ay[q] = -2.0f*qp.y; az[q] = -2.0f*qp.z;
        qw[q] = qp.w;
        lmin[q] = CUDART_INF_F;
        seed[q] = (int)(g_qkey[qbase + q] >> 16);
    }

    // Phase B: scan each DISTINCT seed cluster, updating all 8 lmins
    #pragma unroll
    for (int q = 0; q < GQ; ++q) {
        bool dup = false;
        #pragma unroll
        for (int j = 0; j < GQ; ++j) if (j < q) dup |= (seed[j] == seed[q]);
        if (!dup) {
            int2 sc = shcs[seed[q]];
            for (int o = lane; o < sc.y; o += 32) {
                float4 p = pts[sc.x + o];
                #pragma unroll
                for (int r = 0; r < GQ; ++r) {
                    float t = fmaf(ax[r], p.x, p.w);
                    t = fmaf(ay[r], p.y, t);
                    t = fmaf(az[r], p.z, t);
                    lmin[r] = fminf(lmin[r], t);
                }
            }
        }
    }
    float best[GQ];
    #pragma unroll
    for (int q = 0; q < GQ; ++q)
        best[q] = sqrtf(fmaxf(warpMin(lmin[q]) + qw[q], 0.0f));

    // Phase C1: union candidate list over the 8 queries
    int nc = 0;
    #pragma unroll
    for (int k = 0; k < 32; ++k) {
        const int cid = k*32 + lane;
        float4 c = shc[cid];
        float r = shr[cid];
        bool pred = false;
        #pragma unroll
        for (int q = 0; q < GQ; ++q) {
            float t = fmaf(ax[q], c.x, c.w);
            t = fmaf(ay[q], c.y, t);
            t = fmaf(az[q], c.z, t);
            float thr = best[q] + r;
            pred |= (t + qw[q] < thr*thr);   // empty: c.w=+inf -> never
        }
        pred &= (cid != seed[0]);            // main seed already fully scanned
        unsigned m = __ballot_sync(0xffffffffu, pred);
        if (pred) {
            int off = __popc(m & ((1u << lane) - 1u));
            mylist[nc + off] = (unsigned short)cid;
        }
        nc += __popc(m);
    }
    __syncwarp();

    // Phase C2: scan union list once; 2 clusters in flight; 8 queries per point
    int ci = 0;
    for (; ci + 2 <= nc; ci += 2) {
        int2 s0 = shcs[mylist[ci+0]];
        int2 s1 = shcs[mylist[ci+1]];
        int mx = max(s0.y, s1.y);
        for (int o = lane; o < mx; o += 32) {
            if (o < s0.y) {
                float4 p = pts[s0.x + o];
                #pragma unroll
                for (int q = 0; q < GQ; ++q) {
                    float t = fmaf(ax[q], p.x, p.w);
                    t = fmaf(ay[q], p.y, t);
                    t = fmaf(az[q], p.z, t);
                    lmin[q] = fminf(lmin[q], t);
                }
            }
            if (o < s1.y) {
                float4 p = pts[s1.x + o];
                #pragma unroll
                for (int q = 0; q < GQ; ++q) {
                    float t = fmaf(ax[q], p.x, p.w);
                    t = fmaf(ay[q], p.y, t);
                    t = fmaf(az[q], p.z, t);
                    lmin[q] = fminf(lmin[q], t);
                }
            }
        }
    }
    if (ci < nc) {
        int2 s0 = shcs[mylist[ci]];
        for (int o = lane; o < s0.y; o += 32) {
            float4 p = pts[s0.x + o];
            #pragma unroll
            for (int q = 0; q < GQ; ++q) {
                float t = fmaf(ax[q], p.x, p.w);
                t = fmaf(ay[q], p.y, t);
                t = fmaf(az[q], p.z, t);
                lmin[q] = fminf(lmin[q], t);
            }
        }
    }

    // Write results (original index recovered from the sorted key)
    #pragma unroll
    for (int q = 0; q < GQ; ++q) {
        float best2 = warpMin(lmin[q]) + qw[q];
        if (lane == 0) {
            int qloc = (int)(g_qkey[qbase + q] & 0xFFFFu);
            g_mind[b*MM + qloc] = fmaxf(best2, 0.0f);
        }
    }
}

// Epilogue: one warp per center: max over S, then sum over centers ------------
__global__ void k_c2p() {
    const int lane = threadIdx.x & 31;
    const int wid  = (blockIdx.x * blockDim.x + threadIdx.x) >> 5;  // 0..BB*NCC-1
    float v = sqrtf(fmaxf(g_mind[wid*SS + lane], 1e-12f));
    #pragma unroll
    for (int o = 16; o > 0; o >>= 1)
        v = fmaxf(v, __shfl_xor_sync(0xffffffffu, v, o));
    if (lane == 0) atomicAdd(&g_acc[2 + wid/NCC], v);
}

// Final scalar ----------------------------------------------------------------
__global__ void k_final(float* out) {
    float r = 0.0f;
    #pragma unroll
    for (int b = 0; b < BB; ++b)
        r += g_acc[b] * (1.0f/NN) + g_acc[2 + b] * (1.0f/NCC);
    out[0] = r * (1.0f/BB);
}

// ---------------------------------------------------------------------------
extern "C" void kernel_launch(void* const* d_in, const int* in_sizes, int n_in,
                              void* d_out, int out_size) {
    const float* centers = (const float*)d_in[0];
    const float* radius  = (const float*)d_in[1];
    const float* xyz     = (const float*)d_in[2];
    const float* sp      = (const float*)d_in[3];
    float* out = (float*)d_out;

    k_prep<<<(BB*NN + 255)/256, 256>>>(xyz, centers);
    k_p2c<<<dim3(NN/256, BB), 256>>>(radius);
    k_qprep<<<dim3(MM/256, BB), 256>>>(sp);
    k_scan<<<1, 1024>>>();
    k_scatter<<<(BB*NN)/256, 256>>>();
    k_qscatter<<<(BB*MM)/256, 256>>>(sp);
    k_nn<<<(BB*MM)/QPB, 32*NN_WARPS>>>();
    k_c2p<<<dim3((BB*NCC*32)/256), 256>>>();
    k_final<<<1, 1>>>(out);
}